// round 8
// baseline (speedup 1.0000x reference)
#include <cuda_runtime.h>

#define T_STEPS 2000
#define HID 51
#define FEAT 49
#define NTHR 256

typedef unsigned long long ull;

__device__ __forceinline__ float sigm(float x) {
    return __fdividef(1.0f, 1.0f + __expf(-x));
}
__device__ __forceinline__ float ftanh(float x) {
    return __fdividef(2.0f, 1.0f + __expf(-2.0f * x)) - 1.0f;
}
__device__ __forceinline__ ull pk(float a, float b) {
    ull r;
    asm("mov.b64 %0, {%1, %2};" : "=l"(r) : "f"(a), "f"(b));
    return r;
}
__device__ __forceinline__ ull fma2(ull a, ull b, ull c) {
    ull d;
    asm("fma.rn.f32x2 %0, %1, %2, %3;" : "=l"(d) : "l"(a), "l"(b), "l"(c));
    return d;
}
__device__ __forceinline__ ull add2(ull a, ull b) {
    ull d;
    asm("add.rn.f32x2 %0, %1, %2;" : "=l"(d) : "l"(a), "l"(b));
    return d;
}
__device__ __forceinline__ void upk(ull v, float& a, float& b) {
    asm("mov.b64 {%0, %1}, %2;" : "=f"(a), "=f"(b) : "l"(v));
}

__global__ __launch_bounds__(NTHR, 2)
void lstm_seq_kernel(const float* __restrict__ stim,
                     const float* __restrict__ Wl,   const float* __restrict__ bl,
                     const float* __restrict__ Wih1, const float* __restrict__ Whh1,
                     const float* __restrict__ bih1, const float* __restrict__ bhh1,
                     const float* __restrict__ Wih2, const float* __restrict__ Whh2,
                     const float* __restrict__ bih2, const float* __restrict__ bhh2,
                     const float* __restrict__ Wa,   const float* __restrict__ ba,
                     float* __restrict__ out)
{
    __shared__ float xlin[T_STEPS];                       // 8000 B
    __shared__ __align__(16) float h1_sh[2][52];          // [51] carries xlin[t]
    __shared__ float wl_sh[FEAT];

    const int tid  = threadIdx.x;
    const int lane = tid & 31;
    const int wid  = tid >> 5;
    const int n    = blockIdx.x;

    if (tid < FEAT) wl_sh[tid] = Wl[tid];
    if (tid < 52) { h1_sh[0][tid] = 0.0f; h1_sh[1][tid] = 0.0f; }
    __syncthreads();

    // ---- Phase 0: x_lin = relu(stim . Wl + bl), warp-per-timestep ----
    {
        const float blv = bl[0];
        const float* sb = stim + (size_t)n * T_STEPS * FEAT;
        for (int t = wid; t < T_STEPS; t += 8) {
            const float* p = sb + t * FEAT;
            float s = 0.0f;
            if (lane < FEAT)      s  = p[lane]      * wl_sh[lane];
            if (lane + 32 < FEAT) s += p[lane + 32] * wl_sh[lane + 32];
            #pragma unroll
            for (int off = 16; off; off >>= 1)
                s += __shfl_xor_sync(0xffffffffu, s, off);
            if (lane == 0) xlin[t] = fmaxf(s + blv, 0.0f);
        }
    }

    // ---- Per-thread static weights ----
    // Threads 0..203: thread 4j+g owns gate row g*51+j (g: 0=i,1=f,2=g,3=o).
    // wp[25] = (w50, wih) so x rides as h[51].
    // Warp 7 lanes 0..3: LSTM2 input-projection rows; lane 0: serial LSTM2;
    // lane 4: x-writer (publishes xlin[t+1] into h buffer slot 51).
    const bool is_gate = (tid < 204);
    const int  j   = tid >> 2;
    const int  g   = tid & 3;

    ull   wp[26];
    float bias = 0.0f;
    if (is_gate) {
        const int row = g * HID + j;
        const float* wr = Whh1 + row * HID;
        #pragma unroll
        for (int q = 0; q < 25; q++) wp[q] = pk(wr[2 * q], wr[2 * q + 1]);
        wp[25] = pk(wr[50], Wih1[row]);
        bias = bih1[row] + bhh1[row];
    } else if (wid == 7 && lane < 4) {
        const float* wr = Wih2 + lane * HID;
        #pragma unroll
        for (int q = 0; q < 25; q++) wp[q] = pk(wr[2 * q], wr[2 * q + 1]);
        wp[25] = pk(wr[50], 0.0f);
        bias = bih2[lane] + bhh2[lane];
    }

    float whh2r[4], wav = 0.0f, bav = 0.0f;
    if (wid == 7 && lane < 4) {
        #pragma unroll
        for (int k = 0; k < 4; k++) whh2r[k] = Whh2[k];
        wav = Wa[0];
        bav = ba[0];
    }

    float c1 = 0.0f, h2 = 0.0f, c2 = 0.0f;
    float s0 = 0.0f, s1 = 0.0f, s2 = 0.0f, s3 = 0.0f;
    float* outp = out + (size_t)n * T_STEPS;
    __syncthreads();                       // xlin + weights ready

    if (tid == 0) h1_sh[0][51] = xlin[0];  // seed x for step 0
    __syncthreads();

    const unsigned gmask = (tid < 192) ? 0xffffffffu : 0x0fffu;  // warp6: lanes 0..11

    // ---- Recurrence: T+2 iterations, ONE barrier per iteration ----
    // iter t: gates read {h(t-1), x(t)} = buf[t&1], write h(t) -> buf[(t+1)&1];
    //         warp7 lane4 writes x(t+1) -> buf[(t+1)&1][51];
    //         warp7 lanes0..3: p(t-1) = Wih2 . h(t-1);
    //         warp7 lane0: serial LSTM2 step t-2, writes out[t-2].
    for (int t = 0; t <= T_STEPS + 1; t++) {
        const ulonglong2* h8 = reinterpret_cast<const ulonglong2*>(h1_sh[t & 1]);

        if (is_gate) {
            if (t < T_STEPS) {
                ull a0 = 0, a1 = 0, a2 = 0, a3 = 0;
                #pragma unroll
                for (int q = 0; q < 13; q++) {
                    ulonglong2 v = h8[q];
                    if (q & 1) {
                        a2 = fma2(v.x, wp[2 * q],     a2);
                        a3 = fma2(v.y, wp[2 * q + 1], a3);
                    } else {
                        a0 = fma2(v.x, wp[2 * q],     a0);
                        a1 = fma2(v.y, wp[2 * q + 1], a1);
                    }
                }
                float lo, hi;
                upk(add2(add2(a0, a1), add2(a2, a3)), lo, hi);
                float pre = (lo + hi) + bias;
                float act = (g == 2) ? ftanh(pre) : sigm(pre);

                float v1 = __shfl_xor_sync(gmask, act, 1);
                float v2 = __shfl_xor_sync(gmask, act, 2);
                float v3 = __shfl_xor_sync(gmask, act, 3);
                if (g == 0) {
                    // act=i, v1=f, v2=g, v3=o
                    c1 = v1 * c1 + act * v2;
                    h1_sh[(t + 1) & 1][j] = v3 * ftanh(c1);
                }
            }
        } else if (wid == 7) {
            if (lane < 4) {
                // Serial LSTM2 step t-2 (lane 0; p saved from iter t-1)
                if (t >= 2 && lane == 0) {
                    float gi = sigm (s0 + h2 * whh2r[0]);
                    float gf = sigm (s1 + h2 * whh2r[1]);
                    float gg = ftanh(s2 + h2 * whh2r[2]);
                    float go = sigm (s3 + h2 * whh2r[3]);
                    c2 = gf * c2 + gi * gg;
                    h2 = go * ftanh(c2);
                    outp[t - 2] = h2 * wav + bav;
                }
                // p(t-1) = Wih2 . h(t-1) + bias
                if (t >= 1 && t <= T_STEPS) {
                    ull a0 = 0, a1 = 0;
                    #pragma unroll
                    for (int q = 0; q < 13; q++) {
                        ulonglong2 v = h8[q];
                        a0 = fma2(v.x, wp[2 * q],     a0);
                        a1 = fma2(v.y, wp[2 * q + 1], a1);
                    }
                    float lo, hi;
                    upk(add2(a0, a1), lo, hi);
                    float p = (lo + hi) + bias;
                    float q1 = __shfl_xor_sync(0xfu, p, 1);
                    float q2 = __shfl_xor_sync(0xfu, p, 2);
                    float q3 = __shfl_xor_sync(0xfu, p, 3);
                    s0 = p;  s1 = q1;  s2 = q2;  s3 = q3;    // valid on lane 0
                }
            } else if (lane == 4) {
                if (t + 1 < T_STEPS) h1_sh[(t + 1) & 1][51] = xlin[t + 1];
            }
        }
        __syncthreads();
    }
}

extern "C" void kernel_launch(void* const* d_in, const int* in_sizes, int n_in,
                              void* d_out, int out_size) {
    const float* stim = (const float*)d_in[0];
    const float* Wl   = (const float*)d_in[1];
    const float* bl   = (const float*)d_in[2];
    const float* Wih1 = (const float*)d_in[3];
    const float* Whh1 = (const float*)d_in[4];
    const float* bih1 = (const float*)d_in[5];
    const float* bhh1 = (const float*)d_in[6];
    const float* Wih2 = (const float*)d_in[7];
    const float* Whh2 = (const float*)d_in[8];
    const float* bih2 = (const float*)d_in[9];
    const float* bhh2 = (const float*)d_in[10];
    const float* Wa   = (const float*)d_in[11];
    const float* ba   = (const float*)d_in[12];

    const int N = out_size / T_STEPS;   // 256
    lstm_seq_kernel<<<N, NTHR>>>(stim, Wl, bl, Wih1, Whh1, bih1, bhh1,
                                 Wih2, Whh2, bih2, bhh2, Wa, ba,
                                 (float*)d_out);
}

// round 9
// speedup vs baseline: 1.2466x; 1.2466x over previous
#include <cuda_runtime.h>

#define T_STEPS 2000
#define HID 51
#define FEAT 49
#define NTHR 256

typedef unsigned long long ull;

// Hardware tanh (MUFU.TANH, sm_75+): 1 MUFU op, ~1.3e-4 abs error.
__device__ __forceinline__ float ftanh(float x) {
    float r;
    asm("tanh.approx.f32 %0, %1;" : "=f"(r) : "f"(x));
    return r;
}
// sigmoid via half-angle identity: sigma(x) = 0.5*tanh(x/2) + 0.5
__device__ __forceinline__ float sigm(float x) {
    return fmaf(ftanh(0.5f * x), 0.5f, 0.5f);
}
__device__ __forceinline__ ull pk(float a, float b) {
    ull r;
    asm("mov.b64 %0, {%1, %2};" : "=l"(r) : "f"(a), "f"(b));
    return r;
}
__device__ __forceinline__ ull fma2(ull a, ull b, ull c) {
    ull d;
    asm("fma.rn.f32x2 %0, %1, %2, %3;" : "=l"(d) : "l"(a), "l"(b), "l"(c));
    return d;
}
__device__ __forceinline__ ull add2(ull a, ull b) {
    ull d;
    asm("add.rn.f32x2 %0, %1, %2;" : "=l"(d) : "l"(a), "l"(b));
    return d;
}
__device__ __forceinline__ void upk(ull v, float& a, float& b) {
    asm("mov.b64 {%0, %1}, %2;" : "=f"(a), "=f"(b) : "l"(v));
}

__global__ __launch_bounds__(NTHR, 2)
void lstm_seq_kernel(const float* __restrict__ stim,
                     const float* __restrict__ Wl,   const float* __restrict__ bl,
                     const float* __restrict__ Wih1, const float* __restrict__ Whh1,
                     const float* __restrict__ bih1, const float* __restrict__ bhh1,
                     const float* __restrict__ Wih2, const float* __restrict__ Whh2,
                     const float* __restrict__ bih2, const float* __restrict__ bhh2,
                     const float* __restrict__ Wa,   const float* __restrict__ ba,
                     float* __restrict__ out)
{
    __shared__ float xlin[T_STEPS];                       // 8000 B
    __shared__ __align__(16) float h1_sh[2][52];          // [51] carries xlin[t]
    __shared__ float wl_sh[FEAT];

    const int tid  = threadIdx.x;
    const int lane = tid & 31;
    const int wid  = tid >> 5;
    const int n    = blockIdx.x;

    if (tid < FEAT) wl_sh[tid] = Wl[tid];
    if (tid < 52) { h1_sh[0][tid] = 0.0f; h1_sh[1][tid] = 0.0f; }
    __syncthreads();

    // ---- Phase 0: x_lin = relu(stim . Wl + bl), warp-per-timestep ----
    {
        const float blv = bl[0];
        const float* sb = stim + (size_t)n * T_STEPS * FEAT;
        for (int t = wid; t < T_STEPS; t += 8) {
            const float* p = sb + t * FEAT;
            float s = 0.0f;
            if (lane < FEAT)      s  = p[lane]      * wl_sh[lane];
            if (lane + 32 < FEAT) s += p[lane + 32] * wl_sh[lane + 32];
            #pragma unroll
            for (int off = 16; off; off >>= 1)
                s += __shfl_xor_sync(0xffffffffu, s, off);
            if (lane == 0) xlin[t] = fmaxf(s + blv, 0.0f);
        }
    }

    // ---- Per-thread static weights ----
    // Threads 0..203: thread 4j+g owns gate row g*51+j (g: 0=i,1=f,2=g,3=o).
    // wp[25] = (w50, wih) so x rides as h[51].
    // Warp 7 lanes 0..3: LSTM2 input-projection rows; lane 0: serial LSTM2;
    // lane 4: x-writer (publishes xlin[t+1] into h buffer slot 51).
    const bool is_gate = (tid < 204);
    const int  j   = tid >> 2;
    const int  g   = tid & 3;

    ull   wp[26];
    float bias = 0.0f;
    if (is_gate) {
        const int row = g * HID + j;
        const float* wr = Whh1 + row * HID;
        #pragma unroll
        for (int q = 0; q < 25; q++) wp[q] = pk(wr[2 * q], wr[2 * q + 1]);
        wp[25] = pk(wr[50], Wih1[row]);
        bias = bih1[row] + bhh1[row];
    } else if (wid == 7 && lane < 4) {
        const float* wr = Wih2 + lane * HID;
        #pragma unroll
        for (int q = 0; q < 25; q++) wp[q] = pk(wr[2 * q], wr[2 * q + 1]);
        wp[25] = pk(wr[50], 0.0f);
        bias = bih2[lane] + bhh2[lane];
    }

    float whh2r[4], wav = 0.0f, bav = 0.0f;
    if (wid == 7 && lane < 4) {
        #pragma unroll
        for (int k = 0; k < 4; k++) whh2r[k] = Whh2[k];
        wav = Wa[0];
        bav = ba[0];
    }

    float c1 = 0.0f, h2 = 0.0f, c2 = 0.0f;
    float s0 = 0.0f, s1 = 0.0f, s2 = 0.0f, s3 = 0.0f;
    float* outp = out + (size_t)n * T_STEPS;
    __syncthreads();                       // xlin + weights ready

    if (tid == 0) h1_sh[0][51] = xlin[0];  // seed x for step 0
    __syncthreads();

    const unsigned gmask = (tid < 192) ? 0xffffffffu : 0x0fffu;  // warp6: lanes 0..11

    // ---- Recurrence: T+2 iterations, ONE barrier per iteration ----
    // iter t: gates read {h(t-1), x(t)} = buf[t&1], write h(t) -> buf[(t+1)&1];
    //         warp7 lane4 writes x(t+1) -> buf[(t+1)&1][51];
    //         warp7 lanes0..3: p(t-1) = Wih2 . h(t-1);
    //         warp7 lane0: serial LSTM2 step t-2, writes out[t-2].
    for (int t = 0; t <= T_STEPS + 1; t++) {
        const ulonglong2* h8 = reinterpret_cast<const ulonglong2*>(h1_sh[t & 1]);

        if (is_gate) {
            if (t < T_STEPS) {
                ull a0 = 0, a1 = 0, a2 = 0, a3 = 0;
                #pragma unroll
                for (int q = 0; q < 13; q++) {
                    ulonglong2 v = h8[q];
                    if (q & 1) {
                        a2 = fma2(v.x, wp[2 * q],     a2);
                        a3 = fma2(v.y, wp[2 * q + 1], a3);
                    } else {
                        a0 = fma2(v.x, wp[2 * q],     a0);
                        a1 = fma2(v.y, wp[2 * q + 1], a1);
                    }
                }
                float lo, hi;
                upk(add2(add2(a0, a1), add2(a2, a3)), lo, hi);
                float pre = (lo + hi) + bias;
                float act = (g == 2) ? ftanh(pre) : sigm(pre);

                float v1 = __shfl_xor_sync(gmask, act, 1);
                float v2 = __shfl_xor_sync(gmask, act, 2);
                float v3 = __shfl_xor_sync(gmask, act, 3);
                if (g == 0) {
                    // act=i, v1=f, v2=g, v3=o
                    c1 = v1 * c1 + act * v2;
                    h1_sh[(t + 1) & 1][j] = v3 * ftanh(c1);
                }
            }
        } else if (wid == 7) {
            if (lane < 4) {
                // Serial LSTM2 step t-2 (lane 0; p saved from iter t-1)
                if (t >= 2 && lane == 0) {
                    float gi = sigm (s0 + h2 * whh2r[0]);
                    float gf = sigm (s1 + h2 * whh2r[1]);
                    float gg = ftanh(s2 + h2 * whh2r[2]);
                    float go = sigm (s3 + h2 * whh2r[3]);
                    c2 = gf * c2 + gi * gg;
                    h2 = go * ftanh(c2);
                    outp[t - 2] = h2 * wav + bav;
                }
                // p(t-1) = Wih2 . h(t-1) + bias
                if (t >= 1 && t <= T_STEPS) {
                    ull a0 = 0, a1 = 0;
                    #pragma unroll
                    for (int q = 0; q < 13; q++) {
                        ulonglong2 v = h8[q];
                        a0 = fma2(v.x, wp[2 * q],     a0);
                        a1 = fma2(v.y, wp[2 * q + 1], a1);
                    }
                    float lo, hi;
                    upk(add2(a0, a1), lo, hi);
                    float p = (lo + hi) + bias;
                    float q1 = __shfl_xor_sync(0xfu, p, 1);
                    float q2 = __shfl_xor_sync(0xfu, p, 2);
                    float q3 = __shfl_xor_sync(0xfu, p, 3);
                    s0 = p;  s1 = q1;  s2 = q2;  s3 = q3;    // valid on lane 0
                }
            } else if (lane == 4) {
                if (t + 1 < T_STEPS) h1_sh[(t + 1) & 1][51] = xlin[t + 1];
            }
        }
        __syncthreads();
    }
}

extern "C" void kernel_launch(void* const* d_in, const int* in_sizes, int n_in,
                              void* d_out, int out_size) {
    const float* stim = (const float*)d_in[0];
    const float* Wl   = (const float*)d_in[1];
    const float* bl   = (const float*)d_in[2];
    const float* Wih1 = (const float*)d_in[3];
    const float* Whh1 = (const float*)d_in[4];
    const float* bih1 = (const float*)d_in[5];
    const float* bhh1 = (const float*)d_in[6];
    const float* Wih2 = (const float*)d_in[7];
    const float* Whh2 = (const float*)d_in[8];
    const float* bih2 = (const float*)d_in[9];
    const float* bhh2 = (const float*)d_in[10];
    const float* Wa   = (const float*)d_in[11];
    const float* ba   = (const float*)d_in[12];

    const int N = out_size / T_STEPS;   // 256
    lstm_seq_kernel<<<N, NTHR>>>(stim, Wl, bl, Wih1, Whh1, bih1, bhh1,
                                 Wih2, Whh2, bih2, bhh2, Wa, ba,
                                 (float*)d_out);
}